// round 16
// baseline (speedup 1.0000x reference)
#include <cuda_runtime.h>
#include <math.h>

#define BB   16
#define CC   256
#define HWP  4096      // 64*64
#define NN   256       // patches
#define HEAD 16
#define DD   256
#define KCONV 2304     // 256*9

typedef unsigned long long ull;

// ---------------- f32x2 helpers (Blackwell packed fp32 pipe) -----------------
__device__ __forceinline__ ull pack_dup(float a) {
    ull r; asm("mov.b64 %0, {%1, %1};" : "=l"(r) : "f"(a)); return r;
}
__device__ __forceinline__ ull fma2(ull a, ull b, ull c) {
    ull d; asm("fma.rn.f32x2 %0, %1, %2, %3;" : "=l"(d) : "l"(a), "l"(b), "l"(c)); return d;
}
__device__ __forceinline__ float2 unpack2(ull v) {
    float2 f; asm("mov.b64 {%0, %1}, %2;" : "=f"(f.x), "=f"(f.y) : "l"(v)); return f;
}

// ---------------- scratch (device globals: allocation-free rule) -------------
__device__ float g_q[BB*HEAD*NN*DD];
__device__ float g_k[BB*HEAD*NN*DD];
__device__ float g_v[BB*HEAD*NN*DD];
__device__ float g_s[BB*HEAD*NN*NN];
__device__ float g_attn[BB*CC*HWP];
__device__ float g_out[BB*CC*HWP];
__device__ float g_t1[BB*CC*HWP];
__device__ float g_t2[BB*CC*HWP];
__device__ float g_wqt[CC*CC];
__device__ float g_wkt[CC*CC];
__device__ float g_wvt[CC*CC];
__device__ float g_wot[KCONV*CC];
__device__ float g_w1t[KCONV*CC];
__device__ float g_w2t[KCONV*CC];
__device__ float g_mu1[BB*CC], g_istd1[BB*CC], g_mu2[BB*CC], g_istd2[BB*CC];
__device__ int   g_kmask[BB*NN];

__device__ __forceinline__ float lrelu_f(float v) { return v >= 0.f ? v : 0.2f*v; }

// ---------------- weight transpose: (co, k) -> (k, co) ----------------------
__global__ void transpose_kernel(const float* __restrict__ src, int which, int R, int C)
{
    float* dst = (which==0)?g_wqt:(which==1)?g_wkt:(which==2)?g_wvt:
                 (which==3)?g_wot:(which==4)?g_w1t:g_w2t;
    int i = blockIdx.x*256 + threadIdx.x;
    if (i < R*C) {
        int r = i / C, c = i - r*C;
        dst[c*R + r] = src[i];
    }
}

// ---------------- key mask: patch-mean(mask) < 0.5 ---------------------------
__global__ void mask_kernel(const float* __restrict__ mask)
{
    int idx = blockIdx.x*256 + threadIdx.x;
    if (idx >= BB*NN) return;
    int b = idx >> 8, m = idx & 255;
    int ni = m >> 4, nj = m & 15;
    const float* mb = mask + b*HWP;
    float s = 0.f;
    #pragma unroll
    for (int pi = 0; pi < 4; pi++)
        #pragma unroll
        for (int pj = 0; pj < 4; pj++)
            s += mb[(ni*4+pi)*64 + nj*4+pj];
    g_kmask[idx] = (s*0.0625f < 0.5f) ? 1 : 0;
}

// ---------------- QKV: 1x1 conv GEMM + bias + noise + patchify scatter -------
__global__ __launch_bounds__(256,2) void qkv_kernel(
    const float* __restrict__ x,
    const float* __restrict__ bq_, const float* __restrict__ bk_, const float* __restrict__ bv_,
    const float* __restrict__ nq_, const float* __restrict__ nk_, const float* __restrict__ nv_)
{
    __shared__ __align__(16) float sA[8][132];
    __shared__ __align__(16) float sB[8][132];
    int tid = threadIdx.x;
    int m0 = blockIdx.x*128;
    int n0 = blockIdx.y*128;
    int ws = blockIdx.z >> 4;
    int b  = blockIdx.z & 15;
    const float* wt   = (ws==0)? g_wqt : (ws==1)? g_wkt : g_wvt;
    const float* bias = (ws==0)? bq_ : (ws==1)? bk_ : bv_;
    const float* noi  = (ws==0)? nq_ : (ws==1)? nk_ : nv_;
    float* op = (ws==0)? g_q : (ws==1)? g_k : g_v;
    const float* xb = x + b*CC*HWP;

    int lk = tid >> 5;            // 0..7
    int lm = (tid & 31) << 2;     // 0..124
    int tm = tid & 15, tn = tid >> 4;

    ull acc2[8][4] = {};

    float4 ra = *(const float4*)&xb[lk*HWP + m0 + lm];
    float4 rb = *(const float4*)&wt[lk*CC + n0 + lm];

    for (int kc = 0; kc < CC; kc += 8) {
        __syncthreads();
        *(float4*)&sA[lk][lm] = ra;
        *(float4*)&sB[lk][lm] = rb;
        __syncthreads();
        if (kc + 8 < CC) {
            ra = *(const float4*)&xb[(kc+8+lk)*HWP + m0 + lm];
            rb = *(const float4*)&wt[(kc+8+lk)*CC + n0 + lm];
        }
        #pragma unroll
        for (int kk = 0; kk < 8; kk++) {
            float4 a0 = *(const float4*)&sA[kk][tm*4];
            float4 a1 = *(const float4*)&sA[kk][64 + tm*4];
            ulonglong2 b0 = *(const ulonglong2*)&sB[kk][tn*4];
            ulonglong2 b1 = *(const ulonglong2*)&sB[kk][64 + tn*4];
            ull bv2[4] = {b0.x, b0.y, b1.x, b1.y};
            ull ad[8] = {pack_dup(a0.x), pack_dup(a0.y), pack_dup(a0.z), pack_dup(a0.w),
                         pack_dup(a1.x), pack_dup(a1.y), pack_dup(a1.z), pack_dup(a1.w)};
            #pragma unroll
            for (int i = 0; i < 8; i++)
                #pragma unroll
                for (int j2 = 0; j2 < 4; j2++)
                    acc2[i][j2] = fma2(ad[i], bv2[j2], acc2[i][j2]);
        }
    }

    #pragma unroll
    for (int j2 = 0; j2 < 4; j2++) {
        int co0 = n0 + tn*4 + ((j2&1)<<1) + ((j2>>1)<<6);
        float bs0 = bias[co0], bs1 = bias[co0+1];
        const float* nr0 = noi + (b*CC + co0)*HWP;
        const float* nr1 = nr0 + HWP;
        float* orow = op + (b*HEAD + (co0>>4))*NN*DD;
        int dl0 = (co0 & 15) << 4;
        #pragma unroll
        for (int i = 0; i < 8; i++) {
            int p = m0 + tm*4 + (i&3) + ((i>>2)<<6);
            int y = p >> 6, xx = p & 63;
            int n  = ((y>>2)<<4) + (xx>>2);
            int dd = ((y&3)<<2) + (xx&3);
            float2 f = unpack2(acc2[i][j2]);
            orow[n*DD + dl0 + dd]      = f.x + bs0 + nr0[p];
            orow[n*DD + dl0 + 16 + dd] = f.y + bs1 + nr1[p];
        }
    }
}

// ---------------- GEMM1: S = Q K^T, fused dis-bias/scale/mask ---------------
__global__ __launch_bounds__(256) void gemm1_kernel(const float* __restrict__ dis,
                                                    const float* __restrict__ lap_a)
{
    __shared__ __align__(16) float sA[16][68];
    __shared__ __align__(16) float sB[16][68];
    int tid = threadIdx.x;
    int bh = blockIdx.z;
    int b = bh >> 4;
    const float* Q = g_q + bh*NN*DD;
    const float* K = g_k + bh*NN*DD;
    float* S = g_s + bh*NN*NN;
    int m0 = blockIdx.x*64;
    int n0 = blockIdx.y*64;

    int lr = tid >> 2;
    int lk = (tid & 3) << 2;
    int tm = tid & 15, tn = tid >> 4;

    ull acc2[4][2] = {};
    float4 ra = *(const float4*)&Q[(m0+lr)*DD + lk];
    float4 rb = *(const float4*)&K[(n0+lr)*DD + lk];

    for (int kc = 0; kc < DD; kc += 16) {
        __syncthreads();
        sA[lk+0][lr]=ra.x; sA[lk+1][lr]=ra.y; sA[lk+2][lr]=ra.z; sA[lk+3][lr]=ra.w;
        sB[lk+0][lr]=rb.x; sB[lk+1][lr]=rb.y; sB[lk+2][lr]=rb.z; sB[lk+3][lr]=rb.w;
        __syncthreads();
        if (kc + 16 < DD) {
            ra = *(const float4*)&Q[(m0+lr)*DD + kc+16 + lk];
            rb = *(const float4*)&K[(n0+lr)*DD + kc+16 + lk];
        }
        #pragma unroll
        for (int kk = 0; kk < 16; kk++) {
            float4 a = *(const float4*)&sA[kk][tm*4];
            ulonglong2 bw = *(const ulonglong2*)&sB[kk][tn*4];
            ull ad[4] = {pack_dup(a.x), pack_dup(a.y), pack_dup(a.z), pack_dup(a.w)};
            #pragma unroll
            for (int i = 0; i < 4; i++) {
                acc2[i][0] = fma2(ad[i], bw.x, acc2[i][0]);
                acc2[i][1] = fma2(ad[i], bw.y, acc2[i][1]);
            }
        }
    }
    float la = lap_a[0];
    float sp = fmaxf(la, 0.f) + log1pf(expf(-fabsf(la)));   // softplus
    #pragma unroll
    for (int j2 = 0; j2 < 2; j2++) {
        int m = n0 + tn*4 + j2*2;
        int km0 = g_kmask[b*NN + m];
        int km1 = g_kmask[b*NN + m + 1];
        #pragma unroll
        for (int i = 0; i < 4; i++) {
            int n = m0 + tm*4 + i;
            float2 f = unpack2(acc2[i][j2]);
            float s0 = (f.x + sp * dis[n*NN + m]) * 0.0625f;
            float s1 = (f.y + sp * dis[n*NN + m + 1]) * 0.0625f;
            if (km0) s0 = -1e30f;
            if (km1) s1 = -1e30f;
            S[n*NN + m]     = s0;
            S[n*NN + m + 1] = s1;
        }
    }
}

// ---------------- softmax over last dim (rows of 256), 1 warp / row ----------
__global__ void softmax_kernel()
{
    int row = blockIdx.x*8 + (threadIdx.x >> 5);
    int lane = threadIdx.x & 31;
    float* S = g_s + row*NN;
    float v[8];
    float mx = -1e30f;
    #pragma unroll
    for (int i = 0; i < 8; i++) { v[i] = S[lane + i*32]; mx = fmaxf(mx, v[i]); }
    #pragma unroll
    for (int o = 16; o > 0; o >>= 1) mx = fmaxf(mx, __shfl_xor_sync(0xffffffffu, mx, o));
    float sum = 0.f;
    #pragma unroll
    for (int i = 0; i < 8; i++) { v[i] = expf(v[i] - mx); sum += v[i]; }
    #pragma unroll
    for (int o = 16; o > 0; o >>= 1) sum += __shfl_xor_sync(0xffffffffu, sum, o);
    float inv = 1.f / sum;
    #pragma unroll
    for (int i = 0; i < 8; i++) S[lane + i*32] = v[i]*inv;
}

// ---------------- GEMM2: O = P V, un-patchify scatter to spatial -------------
__global__ __launch_bounds__(256) void gemm2_kernel()
{
    __shared__ __align__(16) float sA[16][68];
    __shared__ __align__(16) float sB[16][68];
    int tid = threadIdx.x;
    int bh = blockIdx.z;
    int b = bh >> 4, h = bh & 15;
    const float* P = g_s + bh*NN*NN;
    const float* V = g_v + bh*NN*DD;
    int m0 = blockIdx.x*64;
    int n0 = blockIdx.y*64;

    int lr = tid >> 2;
    int lk = (tid & 3) << 2;
    int vk = tid >> 4;
    int vd = (tid & 15) << 2;
    int tm = tid & 15, tn = tid >> 4;

    ull acc2[4][2] = {};
    float4 ra = *(const float4*)&P[(m0+lr)*NN + lk];
    float4 rb = *(const float4*)&V[vk*DD + n0 + vd];

    for (int kc = 0; kc < NN; kc += 16) {
        __syncthreads();
        sA[lk+0][lr]=ra.x; sA[lk+1][lr]=ra.y; sA[lk+2][lr]=ra.z; sA[lk+3][lr]=ra.w;
        *(float4*)&sB[vk][vd] = rb;
        __syncthreads();
        if (kc + 16 < NN) {
            ra = *(const float4*)&P[(m0+lr)*NN + kc+16 + lk];
            rb = *(const float4*)&V[(kc+16+vk)*DD + n0 + vd];
        }
        #pragma unroll
        for (int kk = 0; kk < 16; kk++) {
            float4 a = *(const float4*)&sA[kk][tm*4];
            ulonglong2 bw = *(const ulonglong2*)&sB[kk][tn*4];
            ull ad[4] = {pack_dup(a.x), pack_dup(a.y), pack_dup(a.z), pack_dup(a.w)};
            #pragma unroll
            for (int i = 0; i < 4; i++) {
                acc2[i][0] = fma2(ad[i], bw.x, acc2[i][0]);
                acc2[i][1] = fma2(ad[i], bw.y, acc2[i][1]);
            }
        }
    }
    #pragma unroll
    for (int i = 0; i < 4; i++) {
        int n = m0 + tm*4 + i;
        int yhi = (n >> 4) << 2, xhi = (n & 15) << 2;
        #pragma unroll
        for (int j2 = 0; j2 < 2; j2++) {
            int dd0 = n0 + tn*4 + j2*2;
            int c  = (h << 4) + (dd0 >> 4);
            int yy = yhi + ((dd0 >> 2) & 3);
            int xx = xhi + (dd0 & 3);
            float2 f = unpack2(acc2[i][j2]);
            g_attn[(b*CC + c)*HWP + yy*64 + xx]     = f.x;
            g_attn[(b*CC + c)*HWP + yy*64 + xx + 1] = f.y;
        }
    }
}

// ---------------- implicit-GEMM 3x3 conv ------------------------------------
template<int DIL, int MODE>
__device__ __forceinline__ void conv_loadA(const float* __restrict__ inb,
                                           const float* __restrict__ mu,
                                           const float* __restrict__ istd,
                                           int bC, int k, int y, int x0, float ra[4])
{
    int ci = k / 9;
    int r  = k - ci*9;
    int iy  = y  + DIL*((r/3) - 1);
    int ix0 = x0 + DIL*((r%3) - 1);
    bool yok = (iy >= 0) && (iy < 64);
    float m_ = 0.f, is_ = 1.f;
    if (MODE == 2) { m_ = mu[bC+ci]; is_ = istd[bC+ci]; }
    const float* src = inb + ci*HWP + iy*64;
    #pragma unroll
    for (int i = 0; i < 4; i++) {
        int ix = ix0 + i;
        float v = 0.f;
        if (yok && ix >= 0 && ix < 64) {
            v = src[ix];
            if (MODE == 2) v = lrelu_f((v - m_) * is_);
        }
        ra[i] = v;
    }
}

template<int DIL, int MODE>
__global__ __launch_bounds__(256,2) void conv3x3_kernel(const float* __restrict__ bias,
                                                        const float* __restrict__ res)
{
    const float* in = (MODE==0) ? g_attn : (MODE==1) ? g_out : g_t1;
    const float* wt = (MODE==0) ? g_wot  : (MODE==1) ? g_w1t : g_w2t;
    float* out      = (MODE==0) ? g_out  : (MODE==1) ? g_t1  : g_t2;
    const float* mu   = g_mu1;
    const float* istd = g_istd1;

    __shared__ __align__(16) float sA[8][132];
    __shared__ __align__(16) float sB[8][132];
    int tid = threadIdx.x;
    int m0 = blockIdx.x*128;
    int n0 = blockIdx.y*128;
    int b  = blockIdx.z;
    const float* inb = in + b*CC*HWP;

    int lk = tid >> 5;
    int lm = (tid & 31) << 2;
    int p0 = m0 + lm;
    int y  = p0 >> 6, x0 = p0 & 63;
    int tm = tid & 15, tn = tid >> 4;

    ull acc2[8][4] = {};

    float ra[4];
    conv_loadA<DIL,MODE>(inb, mu, istd, b*CC, lk, y, x0, ra);
    float4 rb = *(const float4*)&wt[lk*CC + n0 + lm];

    for (int kc = 0; kc < KCONV; kc += 8) {
        __syncthreads();
        *(float4*)&sA[lk][lm] = make_float4(ra[0], ra[1], ra[2], ra[3]);
        *(float4*)&sB[lk][lm] = rb;
        __syncthreads();
        if (kc + 8 < KCONV) {
            conv_loadA<DIL,MODE>(inb, mu, istd, b*CC, kc+8+lk, y, x0, ra);
            rb = *(const float4*)&wt[(kc+8+lk)*CC + n0 + lm];
        }
        #pragma unroll
        for (int kk = 0; kk < 8; kk++) {
            float4 a0 = *(const float4*)&sA[kk][tm*4];
            float4 a1 = *(const float4*)&sA[kk][64 + tm*4];
            ulonglong2 b0 = *(const ulonglong2*)&sB[kk][tn*4];
            ulonglong2 b1 = *(const ulonglong2*)&sB[kk][64 + tn*4];
            ull bv2[4] = {b0.x, b0.y, b1.x, b1.y};
            ull ad[8] = {pack_dup(a0.x), pack_dup(a0.y), pack_dup(a0.z), pack_dup(a0.w),
                         pack_dup(a1.x), pack_dup(a1.y), pack_dup(a1.z), pack_dup(a1.w)};
            #pragma unroll
            for (int i = 0; i < 8; i++)
                #pragma unroll
                for (int j2 = 0; j2 < 4; j2++)
                    acc2[i][j2] = fma2(ad[i], bv2[j2], acc2[i][j2]);
        }
    }

    #pragma unroll
    for (int j2 = 0; j2 < 4; j2++) {
        int co0 = n0 + tn*4 + ((j2&1)<<1) + ((j2>>1)<<6);
        float bs0 = bias[co0], bs1 = bias[co0+1];
        int base0 = (b*CC + co0)*HWP;
        int base1 = base0 + HWP;
        #pragma unroll
        for (int i = 0; i < 8; i++) {
            int p = m0 + tm*4 + (i&3) + ((i>>2)<<6);
            float2 f = unpack2(acc2[i][j2]);
            float v0 = f.x + bs0;
            float v1 = f.y + bs1;
            if (MODE == 0) {
                v0 = lrelu_f(v0) + res[base0 + p];
                v1 = lrelu_f(v1) + res[base1 + p];
            }
            out[base0 + p] = v0;
            out[base1 + p] = v1;
        }
    }
}

// ---------------- instance-norm stats ----------------------------------------
__global__ void stats_kernel(int which)
{
    const float* t = (which==1) ? g_t1 : g_t2;
    float* mu   = (which==1) ? g_mu1  : g_mu2;
    float* istd = (which==1) ? g_istd1 : g_istd2;
    int bc = blockIdx.x;
    const float* p = t + bc*HWP;
    float s = 0.f, ss = 0.f;
    for (int i = threadIdx.x; i < HWP; i += 256) {
        float v = p[i]; s += v; ss += v*v;
    }
    #pragma unroll
    for (int o = 16; o > 0; o >>= 1) {
        s  += __shfl_xor_sync(0xffffffffu, s, o);
        ss += __shfl_xor_sync(0xffffffffu, ss, o);
    }
    __shared__ float sh[2][8];
    int w = threadIdx.x >> 5;
    if ((threadIdx.x & 31) == 0) { sh[0][w] = s; sh[1][w] = ss; }
    __syncthreads();
    if (threadIdx.x == 0) {
        s = 0.f; ss = 0.f;
        #pragma unroll
        for (int i = 0; i < 8; i++) { s += sh[0][i]; ss += sh[1][i]; }
        float mean = s * (1.f/HWP);
        float var  = ss * (1.f/HWP) - mean*mean;
        mu[bc] = mean;
        istd[bc] = rsqrtf(var + 1e-5f);
    }
}

// ---------------- final: d_out = g_out + lrelu(IN(g_t2)) ---------------------
__global__ void final_kernel(float* __restrict__ dout)
{
    int e = (blockIdx.x*256 + threadIdx.x) << 2;
    int bc = e >> 12;
    float m = g_mu2[bc], is = g_istd2[bc];
    float4 t = *(const float4*)&g_t2[e];
    float4 o = *(const float4*)&g_out[e];
    float4 r;
    r.x = o.x + lrelu_f((t.x - m)*is);
    r.y = o.y + lrelu_f((t.y - m)*is);
    r.z = o.z + lrelu_f((t.z - m)*is);
    r.w = o.w + lrelu_f((t.w - m)*is);
    *(float4*)&dout[e] = r;
}

// ---------------- host driver ------------------------------------------------
extern "C" void kernel_launch(void* const* d_in, const int* in_sizes, int n_in,
                              void* d_out, int out_size)
{
    const float* x     = (const float*)d_in[0];
    const float* mask  = (const float*)d_in[1];
    const float* dis   = (const float*)d_in[2];
    const float* lap_a = (const float*)d_in[3];
    const float* Wq = (const float*)d_in[4];
    const float* bq = (const float*)d_in[5];
    const float* Wk = (const float*)d_in[6];
    const float* bk = (const float*)d_in[7];
    const float* Wv = (const float*)d_in[8];
    const float* bv = (const float*)d_in[9];
    const float* nq = (const float*)d_in[10];
    const float* nk = (const float*)d_in[11];
    const float* nv = (const float*)d_in[12];
    const float* W_out = (const float*)d_in[13];
    const float* b_out = (const float*)d_in[14];
    const float* W1 = (const float*)d_in[15];
    const float* b1 = (const float*)d_in[16];
    const float* W2 = (const float*)d_in[17];
    const float* b2 = (const float*)d_in[18];
    float* out = (float*)d_out;
    (void)n_in; (void)in_sizes; (void)out_size;

    transpose_kernel<<<256, 256>>>(Wq, 0, 256, 256);
    transpose_kernel<<<256, 256>>>(Wk, 1, 256, 256);
    transpose_kernel<<<256, 256>>>(Wv, 2, 256, 256);
    transpose_kernel<<<2304, 256>>>(W_out, 3, 256, KCONV);
    transpose_kernel<<<2304, 256>>>(W1, 4, 256, KCONV);
    transpose_kernel<<<2304, 256>>>(W2, 5, 256, KCONV);
    mask_kernel<<<16, 256>>>(mask);

    dim3 gq(32, 2, 48);
    qkv_kernel<<<gq, 256>>>(x, bq, bk, bv, nq, nk, nv);

    dim3 ga(4, 4, 256);
    gemm1_kernel<<<ga, 256>>>(dis, lap_a);
    softmax_kernel<<<8192, 256>>>();
    gemm2_kernel<<<ga, 256>>>();

    dim3 gc(32, 2, 16);
    conv3x3_kernel<1,0><<<gc, 256>>>(b_out, x);
    conv3x3_kernel<2,1><<<gc, 256>>>(b1, nullptr);
    stats_kernel<<<4096, 256>>>(1);
    conv3x3_kernel<1,2><<<gc, 256>>>(b2, nullptr);
    stats_kernel<<<4096, 256>>>(2);
    final_kernel<<<16384, 256>>>(out);
}

// round 17
// speedup vs baseline: 1.0947x; 1.0947x over previous
#include <cuda_runtime.h>
#include <math.h>

#define BB   16
#define CC   256
#define HWP  4096      // 64*64
#define NN   256       // patches
#define HEAD 16
#define DD   256
#define KCONV 2304     // 256*9

typedef unsigned long long ull;

// ---------------- f32x2 helpers (Blackwell packed fp32 pipe) -----------------
__device__ __forceinline__ ull pack_dup(float a) {
    ull r; asm("mov.b64 %0, {%1, %1};" : "=l"(r) : "f"(a)); return r;
}
__device__ __forceinline__ ull fma2(ull a, ull b, ull c) {
    ull d; asm("fma.rn.f32x2 %0, %1, %2, %3;" : "=l"(d) : "l"(a), "l"(b), "l"(c)); return d;
}
__device__ __forceinline__ float2 unpack2(ull v) {
    float2 f; asm("mov.b64 {%0, %1}, %2;" : "=f"(f.x), "=f"(f.y) : "l"(v)); return f;
}

// ---------------- scratch (device globals: allocation-free rule) -------------
__device__ float g_q[BB*HEAD*NN*DD];
__device__ float g_k[BB*HEAD*NN*DD];
__device__ float g_v[BB*HEAD*NN*DD];
__device__ float g_s[BB*HEAD*NN*NN];
__device__ float g_attn[BB*CC*HWP];
__device__ float g_out[BB*CC*HWP];
__device__ float g_t1[BB*CC*HWP];
__device__ float g_t2[BB*CC*HWP];
__device__ float g_wqt[CC*CC];
__device__ float g_wkt[CC*CC];
__device__ float g_wvt[CC*CC];
__device__ float g_wot[KCONV*CC];
__device__ float g_w1t[KCONV*CC];
__device__ float g_w2t[KCONV*CC];
__device__ float g_mu1[BB*CC], g_istd1[BB*CC], g_mu2[BB*CC], g_istd2[BB*CC];
__device__ int   g_kmask[BB*NN];

__device__ __forceinline__ float lrelu_f(float v) { return v >= 0.f ? v : 0.2f*v; }

// ---------------- fused prep: 6 weight transposes + key mask -----------------
// ranges: [0,64K)x3 qkv weights, then 3x 576K conv weights, then 4K mask
#define P_Q1  65536
#define P_CV  589824
#define P_M0  (3*P_Q1 + 3*P_CV)
#define P_TOT (P_M0 + BB*NN)

__global__ void prep_kernel(const float* __restrict__ Wq, const float* __restrict__ Wk,
                            const float* __restrict__ Wv, const float* __restrict__ Wo,
                            const float* __restrict__ W1, const float* __restrict__ W2,
                            const float* __restrict__ mask)
{
    int i = blockIdx.x*256 + threadIdx.x;
    if (i < 3*P_Q1) {
        int w = i / P_Q1;
        int e = i - w*P_Q1;
        const float* src = (w==0)?Wq:(w==1)?Wk:Wv;
        float* dst = (w==0)?g_wqt:(w==1)?g_wkt:g_wvt;
        int r = e >> 8, c = e & 255;
        dst[c*256 + r] = src[e];
    } else if (i < P_M0) {
        int e = i - 3*P_Q1;
        int w = e / P_CV;
        e -= w*P_CV;
        const float* src = (w==0)?Wo:(w==1)?W1:W2;
        float* dst = (w==0)?g_wot:(w==1)?g_w1t:g_w2t;
        int r = e / KCONV, c = e - r*KCONV;
        dst[c*256 + r] = src[e];
    } else if (i < P_TOT) {
        int idx = i - P_M0;
        int b = idx >> 8, m = idx & 255;
        int ni = m >> 4, nj = m & 15;
        const float* mb = mask + b*HWP;
        float s = 0.f;
        #pragma unroll
        for (int pi = 0; pi < 4; pi++)
            #pragma unroll
            for (int pj = 0; pj < 4; pj++)
                s += mb[(ni*4+pi)*64 + nj*4+pj];
        g_kmask[idx] = (s*0.0625f < 0.5f) ? 1 : 0;
    }
}

// ---------------- QKV: 1x1 conv GEMM + bias + noise + patchify scatter -------
__global__ __launch_bounds__(256,2) void qkv_kernel(
    const float* __restrict__ x,
    const float* __restrict__ bq_, const float* __restrict__ bk_, const float* __restrict__ bv_,
    const float* __restrict__ nq_, const float* __restrict__ nk_, const float* __restrict__ nv_)
{
    __shared__ __align__(16) float sA[8][132];
    __shared__ __align__(16) float sB[8][132];
    int tid = threadIdx.x;
    int m0 = blockIdx.x*128;
    int n0 = blockIdx.y*128;
    int ws = blockIdx.z >> 4;
    int b  = blockIdx.z & 15;
    const float* wt   = (ws==0)? g_wqt : (ws==1)? g_wkt : g_wvt;
    const float* bias = (ws==0)? bq_ : (ws==1)? bk_ : bv_;
    const float* noi  = (ws==0)? nq_ : (ws==1)? nk_ : nv_;
    float* op = (ws==0)? g_q : (ws==1)? g_k : g_v;
    const float* xb = x + b*CC*HWP;

    int lk = tid >> 5;            // 0..7
    int lm = (tid & 31) << 2;     // 0..124
    int tm = tid & 15, tn = tid >> 4;

    ull acc2[8][4] = {};

    float4 ra = *(const float4*)&xb[lk*HWP + m0 + lm];
    float4 rb = *(const float4*)&wt[lk*CC + n0 + lm];

    for (int kc = 0; kc < CC; kc += 8) {
        __syncthreads();
        *(float4*)&sA[lk][lm] = ra;
        *(float4*)&sB[lk][lm] = rb;
        __syncthreads();
        if (kc + 8 < CC) {
            ra = *(const float4*)&xb[(kc+8+lk)*HWP + m0 + lm];
            rb = *(const float4*)&wt[(kc+8+lk)*CC + n0 + lm];
        }
        #pragma unroll
        for (int kk = 0; kk < 8; kk++) {
            float4 a0 = *(const float4*)&sA[kk][tm*4];
            float4 a1 = *(const float4*)&sA[kk][64 + tm*4];
            ulonglong2 b0 = *(const ulonglong2*)&sB[kk][tn*4];
            ulonglong2 b1 = *(const ulonglong2*)&sB[kk][64 + tn*4];
            ull bv2[4] = {b0.x, b0.y, b1.x, b1.y};
            ull ad[8] = {pack_dup(a0.x), pack_dup(a0.y), pack_dup(a0.z), pack_dup(a0.w),
                         pack_dup(a1.x), pack_dup(a1.y), pack_dup(a1.z), pack_dup(a1.w)};
            #pragma unroll
            for (int i = 0; i < 8; i++)
                #pragma unroll
                for (int j2 = 0; j2 < 4; j2++)
                    acc2[i][j2] = fma2(ad[i], bv2[j2], acc2[i][j2]);
        }
    }

    #pragma unroll
    for (int j2 = 0; j2 < 4; j2++) {
        int co0 = n0 + tn*4 + ((j2&1)<<1) + ((j2>>1)<<6);
        float bs0 = bias[co0], bs1 = bias[co0+1];
        const float* nr0 = noi + (b*CC + co0)*HWP;
        const float* nr1 = nr0 + HWP;
        float* orow = op + (b*HEAD + (co0>>4))*NN*DD;
        int dl0 = (co0 & 15) << 4;
        #pragma unroll
        for (int i = 0; i < 8; i++) {
            int p = m0 + tm*4 + (i&3) + ((i>>2)<<6);
            int y = p >> 6, xx = p & 63;
            int n  = ((y>>2)<<4) + (xx>>2);
            int dd = ((y&3)<<2) + (xx&3);
            float2 f = unpack2(acc2[i][j2]);
            orow[n*DD + dl0 + dd]      = f.x + bs0 + nr0[p];
            orow[n*DD + dl0 + 16 + dd] = f.y + bs1 + nr1[p];
        }
    }
}

// ---------------- GEMM1: S = Q K^T, fused dis-bias/scale/mask ---------------
__global__ __launch_bounds__(256) void gemm1_kernel(const float* __restrict__ dis,
                                                    const float* __restrict__ lap_a)
{
    __shared__ __align__(16) float sA[16][68];
    __shared__ __align__(16) float sB[16][68];
    int tid = threadIdx.x;
    int bh = blockIdx.z;
    int b = bh >> 4;
    const float* Q = g_q + bh*NN*DD;
    const float* K = g_k + bh*NN*DD;
    float* S = g_s + bh*NN*NN;
    int m0 = blockIdx.x*64;
    int n0 = blockIdx.y*64;

    int lr = tid >> 2;
    int lk = (tid & 3) << 2;
    int tm = tid & 15, tn = tid >> 4;

    ull acc2[4][2] = {};
    float4 ra = *(const float4*)&Q[(m0+lr)*DD + lk];
    float4 rb = *(const float4*)&K[(n0+lr)*DD + lk];

    for (int kc = 0; kc < DD; kc += 16) {
        __syncthreads();
        sA[lk+0][lr]=ra.x; sA[lk+1][lr]=ra.y; sA[lk+2][lr]=ra.z; sA[lk+3][lr]=ra.w;
        sB[lk+0][lr]=rb.x; sB[lk+1][lr]=rb.y; sB[lk+2][lr]=rb.z; sB[lk+3][lr]=rb.w;
        __syncthreads();
        if (kc + 16 < DD) {
            ra = *(const float4*)&Q[(m0+lr)*DD + kc+16 + lk];
            rb = *(const float4*)&K[(n0+lr)*DD + kc+16 + lk];
        }
        #pragma unroll
        for (int kk = 0; kk < 16; kk++) {
            float4 a = *(const float4*)&sA[kk][tm*4];
            ulonglong2 bw = *(const ulonglong2*)&sB[kk][tn*4];
            ull ad[4] = {pack_dup(a.x), pack_dup(a.y), pack_dup(a.z), pack_dup(a.w)};
            #pragma unroll
            for (int i = 0; i < 4; i++) {
                acc2[i][0] = fma2(ad[i], bw.x, acc2[i][0]);
                acc2[i][1] = fma2(ad[i], bw.y, acc2[i][1]);
            }
        }
    }
    float la = lap_a[0];
    float sp = fmaxf(la, 0.f) + log1pf(expf(-fabsf(la)));   // softplus
    #pragma unroll
    for (int j2 = 0; j2 < 2; j2++) {
        int m = n0 + tn*4 + j2*2;
        int km0 = g_kmask[b*NN + m];
        int km1 = g_kmask[b*NN + m + 1];
        #pragma unroll
        for (int i = 0; i < 4; i++) {
            int n = m0 + tm*4 + i;
            float2 f = unpack2(acc2[i][j2]);
            float s0 = (f.x + sp * dis[n*NN + m]) * 0.0625f;
            float s1 = (f.y + sp * dis[n*NN + m + 1]) * 0.0625f;
            if (km0) s0 = -1e30f;
            if (km1) s1 = -1e30f;
            S[n*NN + m]     = s0;
            S[n*NN + m + 1] = s1;
        }
    }
}

// ---------------- softmax over last dim (rows of 256), 1 warp / row ----------
__global__ void softmax_kernel()
{
    int row = blockIdx.x*8 + (threadIdx.x >> 5);
    int lane = threadIdx.x & 31;
    float* S = g_s + row*NN;
    float v[8];
    float mx = -1e30f;
    #pragma unroll
    for (int i = 0; i < 8; i++) { v[i] = S[lane + i*32]; mx = fmaxf(mx, v[i]); }
    #pragma unroll
    for (int o = 16; o > 0; o >>= 1) mx = fmaxf(mx, __shfl_xor_sync(0xffffffffu, mx, o));
    float sum = 0.f;
    #pragma unroll
    for (int i = 0; i < 8; i++) { v[i] = expf(v[i] - mx); sum += v[i]; }
    #pragma unroll
    for (int o = 16; o > 0; o >>= 1) sum += __shfl_xor_sync(0xffffffffu, sum, o);
    float inv = 1.f / sum;
    #pragma unroll
    for (int i = 0; i < 8; i++) S[lane + i*32] = v[i]*inv;
}

// ---------------- GEMM2: O = P V, un-patchify scatter to spatial -------------
__global__ __launch_bounds__(256) void gemm2_kernel()
{
    __shared__ __align__(16) float sA[16][68];
    __shared__ __align__(16) float sB[16][68];
    int tid = threadIdx.x;
    int bh = blockIdx.z;
    int b = bh >> 4, h = bh & 15;
    const float* P = g_s + bh*NN*NN;
    const float* V = g_v + bh*NN*DD;
    int m0 = blockIdx.x*64;
    int n0 = blockIdx.y*64;

    int lr = tid >> 2;
    int lk = (tid & 3) << 2;
    int vk = tid >> 4;
    int vd = (tid & 15) << 2;
    int tm = tid & 15, tn = tid >> 4;

    ull acc2[4][2] = {};
    float4 ra = *(const float4*)&P[(m0+lr)*NN + lk];
    float4 rb = *(const float4*)&V[vk*DD + n0 + vd];

    for (int kc = 0; kc < NN; kc += 16) {
        __syncthreads();
        sA[lk+0][lr]=ra.x; sA[lk+1][lr]=ra.y; sA[lk+2][lr]=ra.z; sA[lk+3][lr]=ra.w;
        *(float4*)&sB[vk][vd] = rb;
        __syncthreads();
        if (kc + 16 < NN) {
            ra = *(const float4*)&P[(m0+lr)*NN + kc+16 + lk];
            rb = *(const float4*)&V[(kc+16+vk)*DD + n0 + vd];
        }
        #pragma unroll
        for (int kk = 0; kk < 16; kk++) {
            float4 a = *(const float4*)&sA[kk][tm*4];
            ulonglong2 bw = *(const ulonglong2*)&sB[kk][tn*4];
            ull ad[4] = {pack_dup(a.x), pack_dup(a.y), pack_dup(a.z), pack_dup(a.w)};
            #pragma unroll
            for (int i = 0; i < 4; i++) {
                acc2[i][0] = fma2(ad[i], bw.x, acc2[i][0]);
                acc2[i][1] = fma2(ad[i], bw.y, acc2[i][1]);
            }
        }
    }
    #pragma unroll
    for (int i = 0; i < 4; i++) {
        int n = m0 + tm*4 + i;
        int yhi = (n >> 4) << 2, xhi = (n & 15) << 2;
        #pragma unroll
        for (int j2 = 0; j2 < 2; j2++) {
            int dd0 = n0 + tn*4 + j2*2;
            int c  = (h << 4) + (dd0 >> 4);
            int yy = yhi + ((dd0 >> 2) & 3);
            int xx = xhi + (dd0 & 3);
            float2 f = unpack2(acc2[i][j2]);
            g_attn[(b*CC + c)*HWP + yy*64 + xx]     = f.x;
            g_attn[(b*CC + c)*HWP + yy*64 + xx + 1] = f.y;
        }
    }
}

// ---------------- implicit-GEMM 3x3 conv, channel-staged patches -------------
// per-ci: stage zero-padded (2+2*DIL)x68 pixel patch + 9x128 weight slice in
// smem, then 9 fully-unrolled taps with aligned LDS.128 window reuse.
// MODE 0: in=g_attn, out=g_out = lrelu(conv)+res     (dil 1)
// MODE 1: in=g_out,  out=g_t1 raw                    (dil 2)
// MODE 2: in=g_t1 with IN+lrelu transform, out=g_t2  (dil 1)
template<int DIL, int MODE>
__device__ __forceinline__ void stage_load(const float* __restrict__ inb,
                                           const float* __restrict__ wt,
                                           const float* __restrict__ mu,
                                           const float* __restrict__ istd,
                                           int bC, int ci, int y0, int n0, int tid,
                                           float stA[2], float4 stB[2])
{
    constexpr int PR = 2 + 2*DIL;
    float m_ = 0.f, is_ = 1.f;
    if (MODE == 2) { m_ = mu[bC+ci]; is_ = istd[bC+ci]; }
    const float* src = inb + ci*HWP;
    #pragma unroll
    for (int it = 0; it < (PR*64 + 255)/256; it++) {
        int e = tid + it*256;
        float v = 0.f;
        if ((PR*64 % 256) == 0 || e < PR*64) {
            int pr = e >> 6, px = e & 63;
            int gy = y0 - DIL + pr;
            if (gy >= 0 && gy < 64) {
                v = src[gy*64 + px];
                if (MODE == 2) v = lrelu_f((v - m_) * is_);
            }
        }
        stA[it] = v;
    }
    const float* wrow = wt + ci*9*CC + n0;
    stB[0] = *(const float4*)&wrow[(tid >> 5)*CC + ((tid & 31) << 2)];
    if (tid < 32)
        stB[1] = *(const float4*)&wrow[8*CC + (tid << 2)];
}

template<int DIL, int MODE>
__global__ __launch_bounds__(256,2) void conv3x3_kernel(const float* __restrict__ bias,
                                                        const float* __restrict__ res)
{
    constexpr int PR = 2 + 2*DIL;
    const float* in = (MODE==0) ? g_attn : (MODE==1) ? g_out : g_t1;
    const float* wt = (MODE==0) ? g_wot  : (MODE==1) ? g_w1t : g_w2t;
    float* out      = (MODE==0) ? g_out  : (MODE==1) ? g_t1  : g_t2;

    __shared__ __align__(16) float sP[PR][68];
    __shared__ __align__(16) float sB[9][132];

    int tid = threadIdx.x;
    int m0 = blockIdx.x*128;
    int n0 = blockIdx.y*128;
    int b  = blockIdx.z;
    int y0 = m0 >> 6;                  // two output rows y0, y0+1
    const float* inb = in + b*CC*HWP;
    int bC = b*CC;

    int tm = tid & 15, tn = tid >> 4;

    // zero the patch once; borders stay zero for all ci
    for (int e = tid; e < PR*68; e += 256) ((float*)sP)[e] = 0.f;

    ull acc2[8][4] = {};
    float stA[2]; float4 stB[2];
    stage_load<DIL,MODE>(inb, wt, g_mu1, g_istd1, bC, 0, y0, n0, tid, stA, stB);

    for (int ci = 0; ci < CC; ci++) {
        __syncthreads();
        // commit staged data
        #pragma unroll
        for (int it = 0; it < (PR*64 + 255)/256; it++) {
            int e = tid + it*256;
            if ((PR*64 % 256) == 0 || e < PR*64)
                sP[e >> 6][DIL + (e & 63)] = stA[it];
        }
        *(float4*)&sB[tid >> 5][(tid & 31) << 2] = stB[0];
        if (tid < 32) *(float4*)&sB[8][tid << 2] = stB[1];
        __syncthreads();

        if (ci + 1 < CC)
            stage_load<DIL,MODE>(inb, wt, g_mu1, g_istd1, bC, ci+1, y0, n0, tid, stA, stB);

        #pragma unroll
        for (int dy = 0; dy < 3; dy++) {
            float4 r0a = *(const float4*)&sP[dy*DIL][tm*4];
            float4 r0b = *(const float4*)&sP[dy*DIL][tm*4 + 4];
            float4 r1a = *(const float4*)&sP[dy*DIL + 1][tm*4];
            float4 r1b = *(const float4*)&sP[dy*DIL + 1][tm*4 + 4];
            float a0[8] = {r0a.x,r0a.y,r0a.z,r0a.w, r0b.x,r0b.y,r0b.z,r0b.w};
            float a1[8] = {r1a.x,r1a.y,r1a.z,r1a.w, r1b.x,r1b.y,r1b.z,r1b.w};
            #pragma unroll
            for (int dx = 0; dx < 3; dx++) {
                int r = dy*3 + dx;
                int o = dx*DIL;
                ulonglong2 b0 = *(const ulonglong2*)&sB[r][tn*4];
                ulonglong2 b1 = *(const ulonglong2*)&sB[r][64 + tn*4];
                ull bv2[4] = {b0.x, b0.y, b1.x, b1.y};
                ull ad[8] = {pack_dup(a0[o+0]), pack_dup(a0[o+1]),
                             pack_dup(a0[o+2]), pack_dup(a0[o+3]),
                             pack_dup(a1[o+0]), pack_dup(a1[o+1]),
                             pack_dup(a1[o+2]), pack_dup(a1[o+3])};
                #pragma unroll
                for (int i = 0; i < 8; i++)
                    #pragma unroll
                    for (int j2 = 0; j2 < 4; j2++)
                        acc2[i][j2] = fma2(ad[i], bv2[j2], acc2[i][j2]);
            }
        }
    }

    #pragma unroll
    for (int j2 = 0; j2 < 4; j2++) {
        int co0 = n0 + tn*4 + ((j2&1)<<1) + ((j2>>1)<<6);
        float bs0 = bias[co0], bs1 = bias[co0+1];
        int base0 = (bC + co0)*HWP;
        int base1 = base0 + HWP;
        #pragma unroll
        for (int i = 0; i < 8; i++) {
            int p = m0 + tm*4 + (i&3) + ((i>>2)<<6);
            float2 f = unpack2(acc2[i][j2]);
            float v0 = f.x + bs0;
            float v1 = f.y + bs1;
            if (MODE == 0) {
                v0 = lrelu_f(v0) + res[base0 + p];
                v1 = lrelu_f(v1) + res[base1 + p];
            }
            out[base0 + p] = v0;
            out[base1 + p] = v1;
        }
    }
}

// ---------------- instance-norm stats ----------------------------------------
__global__ void stats_kernel(int which)
{
    const float* t = (which==1) ? g_t1 : g_t2;
    float* mu   = (which==1) ? g_mu1  : g_mu2;
    float* istd = (which==1) ? g_istd1 : g_istd2;
    int bc = blockIdx.x;
    const float* p = t + bc*HWP;
    float s = 0.f, ss = 0.f;
    for (int i = threadIdx.x; i < HWP; i += 256) {
        float v = p[i]; s += v; ss += v*v;
    }
    #pragma unroll
    for (int o = 16; o > 0; o >>= 1) {
        s  += __shfl_xor_sync(0xffffffffu, s, o);
        ss += __shfl_xor_sync(0xffffffffu, ss, o);
    }
    __shared__ float sh[2][8];
    int w = threadIdx.x >> 5;
    if ((threadIdx.x & 31) == 0) { sh[0][w] = s; sh[1][w] = ss; }
    __syncthreads();
    if (threadIdx.x == 0) {
        s = 0.f; ss = 0.f;
        #pragma unroll
        for (int i = 0; i < 8; i++) { s += sh[0][i]; ss += sh[1][i]; }
        float mean = s * (1.f/HWP);
        float var  = ss * (1.f/HWP) - mean*mean;
        mu[bc] = mean;
        istd[bc] = rsqrtf(var + 1e-5f);
    }
}

// ---------------- final: d_out = g_out + lrelu(IN(g_t2)) ---------------------
__global__ void final_kernel(float* __restrict__ dout)
{
    int e = (blockIdx.x*256 + threadIdx.x) << 2;
    int bc = e >> 12;
    float m = g_mu2[bc], is = g_istd2[bc];
    float4 t = *(const float4*)&g_t2[e];
    float4 o = *(const float4*)&g_out[e];
    float4 r;
    r.x = o.x + lrelu_f((t.x - m)*is);
    r.y = o.y + lrelu_f((t.y - m)*is);
    r.z = o.z + lrelu_f((t.z - m)*is);
    r.w = o.w + lrelu_f((t.w - m)*is);
    *(float4*)&dout[e] = r;
}

// ---------------- host driver ------------------------------------------------
extern "C" void kernel_launch(void* const* d_in, const int* in_sizes, int n_in,
                              void* d_out, int out_size)
{
    const float* x     = (const float*)d_in[0];
    const float* mask  = (const float*)d_in[1];
    const float* dis   = (const float*)d_in[2];
    const float* lap_a = (const float*)d_in[3];
    const float* Wq = (const float*)d_in[4];
    const float* bq = (const float*)d_in[5];
    const float* Wk = (const float*)d_in[6];
    const float* bk = (const float*)d_in[7];
    const float* Wv = (const float*)d_in[8];
    const float* bv = (const float*)d_in[9];
    const float* nq = (const float*)d_in[10];
    const float* nk = (const float*)d_in[11];
    const float* nv = (const float*)d_in[12];
    const float* W_out = (const float*)d_in[13];
    const float* b_out = (const float*)d_in[14];
    const float* W1 = (const float*)d_in[15];
    const float* b1 = (const float*)d_in[16];
    const float* W2 = (const float*)d_in[17];
    const float* b2 = (const float*)d_in[18];
    float* out = (float*)d_out;
    (void)n_in; (void)in_sizes; (void)out_size;

    // launch 0: fused prep (transposes + mask)
    prep_kernel<<<(P_TOT + 255)/256, 256>>>(Wq, Wk, Wv, W_out, W1, W2, mask);

    // launch 1
    dim3 gq(32, 2, 48);
    qkv_kernel<<<gq, 256>>>(x, bq, bk, bv, nq, nk, nv);

    // launches 2-4
    dim3 ga(4, 4, 256);
    gemm1_kernel<<<ga, 256>>>(dis, lap_a);
    softmax_kernel<<<8192, 256>>>();
    gemm2_kernel<<<ga, 256>>>();

    // launch 5 (ncu -s 5 -c 1 profiles this one)
    dim3 gc(32, 2, 16);
    conv3x3_kernel<1,0><<<gc, 256>>>(b_out, x);
    conv3x3_kernel<2,1><<<gc, 256>>>(b1, nullptr);
    stats_kernel<<<4096, 256>>>(1);
    conv3x3_kernel<1,2><<<gc, 256>>>(b2, nullptr);
    stats_kernel<<<4096, 256>>>(2);
    final_kernel<<<16384, 256>>>(out);
}